// round 1
// baseline (speedup 1.0000x reference)
#include <cuda_runtime.h>
#include <math.h>

// ----- problem dims -----
#define B_    32
#define T_    100
#define NN_   32
#define F_    8
#define D_    256
#define LH    512
#define G4    2048      // 4*LH
#define ROWS  3200      // B_*T_   (row index = t*32 + b)

// ----- device scratch (no allocations allowed) -----
__device__ float d_G  [ROWS * D_];   // relu'd gcn mean embedding
__device__ float d_V  [ROWS * D_];   // value projection
__device__ float d_ATT[ROWS * D_];   // attn_out (== agg)
__device__ float d_X  [ROWS * G4];   // x-projection into LSTM gates
__device__ float d_bihh[G4];         // b_ih + b_hh
__device__ float d_hbuf[2][B_ * LH]; // double-buffered hidden state
__device__ float d_cst [B_ * LH];    // cell state
__device__ float d_L  [ROWS * LH];   // lstm outputs
__device__ float d_H1 [ROWS * D_];   // relu(lin1)

// ======================================================================
// init: zero h[0], c
// ======================================================================
__global__ void k_zero() {
    int i = blockIdx.x * blockDim.x + threadIdx.x;
    if (i < B_ * LH) {
        d_hbuf[0][i] = 0.0f;
        d_cst[i]     = 0.0f;
    }
}

// d_bihh = b_ih + b_hh
__global__ void k_bihh(const float* __restrict__ bih, const float* __restrict__ bhh) {
    int i = blockIdx.x * blockDim.x + threadIdx.x;
    if (i < G4) d_bihh[i] = bih[i] + bhh[i];
}

// ======================================================================
// G[row,d] = relu( (mean_n traj[b,t,n,:]) @ gcn_w + gcn_b )
// one block per (t,b) row, 256 threads
// ======================================================================
__global__ void k_G(const float* __restrict__ traj,
                    const float* __restrict__ gw,
                    const float* __restrict__ gb) {
    int row = blockIdx.x;            // t*32 + b
    int t = row >> 5, b = row & 31;
    __shared__ float s[NN_ * F_];
    __shared__ float m[F_];
    int tid = threadIdx.x;

    const float* p = traj + (size_t)((b * T_ + t) * NN_) * F_;
    s[tid] = p[tid];                 // 256 contiguous floats
    __syncthreads();
    if (tid < F_) {
        float acc = 0.0f;
        #pragma unroll
        for (int n = 0; n < NN_; n++) acc += s[n * F_ + tid];
        m[tid] = acc * (1.0f / 32.0f);
    }
    __syncthreads();
    float acc = gb[tid];
    #pragma unroll
    for (int f = 0; f < F_; f++) acc += m[f] * gw[f * D_ + tid];
    d_G[(size_t)row * D_ + tid] = fmaxf(acc, 0.0f);
}

// ======================================================================
// SGEMM-NT:  C[M,N] = A[M,K] @ B[N,K]^T + bias[N]
// flags: 1 = relu epilogue, 2 = permute rows (t*32+b -> (b*T+t)) on store
// BM=BN=128, BK=16, 256 threads, 8x8 micro-tile.
// All call sites have M%128==0, N%128==0, K%16==0 — no bounds checks.
// ======================================================================
__global__ void __launch_bounds__(256)
sgemm_nt(const float* __restrict__ A, const float* __restrict__ Bm,
         const float* __restrict__ bias, float* __restrict__ C,
         int M, int N, int K, int flags) {
    __shared__ __align__(16) float As[16][128];
    __shared__ __align__(16) float Bs[16][128];

    int tid = threadIdx.x;
    int m0 = blockIdx.y * 128;
    int n0 = blockIdx.x * 128;
    int tm = (tid >> 4) * 8;     // 0..120
    int tn = (tid & 15) * 8;     // 0..120

    float acc[8][8];
    #pragma unroll
    for (int i = 0; i < 8; i++)
        #pragma unroll
        for (int j = 0; j < 8; j++) acc[i][j] = 0.0f;

    for (int k0 = 0; k0 < K; k0 += 16) {
        // load A tile 128x16 (transposed into As[k][m]) and B tile likewise
        #pragma unroll
        for (int i = 0; i < 2; i++) {
            int idx = tid + i * 256;        // 0..511
            int r  = idx >> 2;              // 0..127
            int kq = (idx & 3) * 4;         // 0,4,8,12
            float4 va = *(const float4*)&A [(size_t)(m0 + r) * K + k0 + kq];
            As[kq + 0][r] = va.x; As[kq + 1][r] = va.y;
            As[kq + 2][r] = va.z; As[kq + 3][r] = va.w;
            float4 vb = *(const float4*)&Bm[(size_t)(n0 + r) * K + k0 + kq];
            Bs[kq + 0][r] = vb.x; Bs[kq + 1][r] = vb.y;
            Bs[kq + 2][r] = vb.z; Bs[kq + 3][r] = vb.w;
        }
        __syncthreads();
        #pragma unroll
        for (int kk = 0; kk < 16; kk++) {
            float a[8], b[8];
            *(float4*)&a[0] = *(const float4*)&As[kk][tm];
            *(float4*)&a[4] = *(const float4*)&As[kk][tm + 4];
            *(float4*)&b[0] = *(const float4*)&Bs[kk][tn];
            *(float4*)&b[4] = *(const float4*)&Bs[kk][tn + 4];
            #pragma unroll
            for (int i = 0; i < 8; i++)
                #pragma unroll
                for (int j = 0; j < 8; j++)
                    acc[i][j] += a[i] * b[j];
        }
        __syncthreads();
    }

    // epilogue
    #pragma unroll
    for (int i = 0; i < 8; i++) {
        int m = m0 + tm + i;
        float* crow;
        if (flags & 2) {
            int b = m & 31, tt = m >> 5;
            crow = C + (size_t)(b * T_ + tt) * N;
        } else {
            crow = C + (size_t)m * N;
        }
        #pragma unroll
        for (int j = 0; j < 8; j += 4) {
            float4 v;
            v.x = acc[i][j + 0] + bias[n0 + tn + j + 0];
            v.y = acc[i][j + 1] + bias[n0 + tn + j + 1];
            v.z = acc[i][j + 2] + bias[n0 + tn + j + 2];
            v.w = acc[i][j + 3] + bias[n0 + tn + j + 3];
            if (flags & 1) {
                v.x = fmaxf(v.x, 0.0f); v.y = fmaxf(v.y, 0.0f);
                v.z = fmaxf(v.z, 0.0f); v.w = fmaxf(v.w, 0.0f);
            }
            *(float4*)&crow[n0 + tn + j] = v;
        }
    }
}

// ======================================================================
// LSTM step t (fused gates GEMM + pointwise).
// Grid: 128 blocks, 128 threads. Block bid owns hidden units j0=bid*4..+3
// for ALL 4 gates (rows {g*512 + j}), so the c/h update is block-local.
// Z = h_prev @ w_hh^T + X[t];  per-block MACs = 16 rows * 32 b * 512 k.
// h double-buffered across t to avoid cross-block read/write races.
// ======================================================================
__global__ void __launch_bounds__(128)
k_step(const float* __restrict__ whh, int t) {
    __shared__ __align__(16) float hT[64][36];  // [k][b], padded
    __shared__ __align__(16) float ws[16][64];  // [row_local][k]
    __shared__ __align__(16) float zb[16][32];  // [row_local][b]

    int tid = threadIdx.x;
    int j0  = blockIdx.x * 4;
    int nl  = tid >> 3;                 // 0..15  row_local = gate*4 + jj
    int b4  = (tid & 7) * 4;            // batch quad base
    int gate = nl >> 2, jj = nl & 3;
    int rown = gate * LH + j0 + jj;     // row in w_hh / X gate dim

    const float* hin  = d_hbuf[t & 1];
    float*       hout = d_hbuf[(t + 1) & 1];

    float acc[4];
    #pragma unroll
    for (int i = 0; i < 4; i++)
        acc[i] = d_X[(size_t)(t * 32 + b4 + i) * G4 + rown];

    for (int k0 = 0; k0 < LH; k0 += 64) {
        __syncthreads();
        // stage h (32 x 64) transposed
        #pragma unroll
        for (int i = 0; i < 16; i++) {
            int idx = tid + i * 128;     // 0..2047
            int bb = idx >> 6, kk = idx & 63;
            hT[kk][bb] = hin[bb * LH + k0 + kk];
        }
        // stage w_hh tile (16 rows x 64)
        #pragma unroll
        for (int i = 0; i < 8; i++) {
            int idx = tid + i * 128;     // 0..1023
            int nn = idx >> 6, kk = idx & 63;
            int rr = (nn >> 2) * LH + j0 + (nn & 3);
            ws[nn][kk] = whh[(size_t)rr * LH + k0 + kk];
        }
        __syncthreads();
        #pragma unroll 4
        for (int kk = 0; kk < 64; kk++) {
            float4 hv = *(const float4*)&hT[kk][b4];
            float  w  = ws[nl][kk];
            acc[0] += hv.x * w; acc[1] += hv.y * w;
            acc[2] += hv.z * w; acc[3] += hv.w * w;
        }
    }

    *(float4*)&zb[nl][b4] = make_float4(acc[0], acc[1], acc[2], acc[3]);
    __syncthreads();

    // pointwise: thread -> (jj2, b)
    int jj2 = tid >> 5, b = tid & 31;
    float zi = zb[0 + jj2][b];
    float zf = zb[4 + jj2][b];
    float zg = zb[8 + jj2][b];
    float zo = zb[12 + jj2][b];
    int j = j0 + jj2;
    float cp = d_cst[b * LH + j];
    float ig = 1.0f / (1.0f + expf(-zi));
    float fg = 1.0f / (1.0f + expf(-zf));
    float gg = tanhf(zg);
    float og = 1.0f / (1.0f + expf(-zo));
    float cn = fg * cp + ig * gg;
    float hn = og * tanhf(cn);
    d_cst[b * LH + j]  = cn;
    hout[b * LH + j]   = hn;
    d_L[(size_t)(t * 32 + b) * LH + j] = hn;
}

// ======================================================================
// host side
// ======================================================================
extern "C" void kernel_launch(void* const* d_in, const int* in_sizes, int n_in,
                              void* d_out, int out_size) {
    const float* traj      = (const float*)d_in[0];
    const float* gcn_w     = (const float*)d_in[1];
    const float* gcn_b     = (const float*)d_in[2];
    const float* in_proj_w = (const float*)d_in[3];
    const float* in_proj_b = (const float*)d_in[4];
    const float* out_proj_w= (const float*)d_in[5];
    const float* out_proj_b= (const float*)d_in[6];
    // d_in[7] = va_w, d_in[8] = va_b : provably unused (uniform softmaxes)
    const float* w_ih      = (const float*)d_in[9];
    const float* w_hh      = (const float*)d_in[10];
    const float* b_ih      = (const float*)d_in[11];
    const float* b_hh      = (const float*)d_in[12];
    const float* lin1_w    = (const float*)d_in[13];
    const float* lin1_b    = (const float*)d_in[14];
    const float* lin2_w    = (const float*)d_in[15];
    const float* lin2_b    = (const float*)d_in[16];
    float* out = (float*)d_out;

    // device-global scratch addresses (host API, not stream-ordered: capture-safe)
    float *pG, *pV, *pATT, *pX, *pbihh, *pL, *pH1;
    cudaGetSymbolAddress((void**)&pG,    d_G);
    cudaGetSymbolAddress((void**)&pV,    d_V);
    cudaGetSymbolAddress((void**)&pATT,  d_ATT);
    cudaGetSymbolAddress((void**)&pX,    d_X);
    cudaGetSymbolAddress((void**)&pbihh, d_bihh);
    cudaGetSymbolAddress((void**)&pL,    d_L);
    cudaGetSymbolAddress((void**)&pH1,   d_H1);

    k_zero<<<(B_ * LH + 255) / 256, 256>>>();
    k_bihh<<<(G4 + 255) / 256, 256>>>(b_ih, b_hh);
    k_G<<<ROWS, 256>>>(traj, gcn_w, gcn_b);

    // V = G @ Wv^T + bv          (Wv = in_proj_w rows [512:768))
    sgemm_nt<<<dim3(D_ / 128, ROWS / 128), 256>>>(
        pG, in_proj_w + (size_t)2 * D_ * D_, in_proj_b + 2 * D_, pV,
        ROWS, D_, D_, 0);
    // ATT = V @ Wop^T + bop      (== agg, collapsed attention)
    sgemm_nt<<<dim3(D_ / 128, ROWS / 128), 256>>>(
        pV, out_proj_w, out_proj_b, pATT, ROWS, D_, D_, 0);
    // X = ATT @ w_ih^T + (b_ih+b_hh)
    sgemm_nt<<<dim3(G4 / 128, ROWS / 128), 256>>>(
        pATT, w_ih, pbihh, pX, ROWS, G4, D_, 0);

    // LSTM: 100 sequential fused-step launches
    for (int t = 0; t < T_; t++)
        k_step<<<128, 128>>>(w_hh, t);

    // MLP
    sgemm_nt<<<dim3(D_ / 128, ROWS / 128), 256>>>(
        pL, lin1_w, lin1_b, pH1, ROWS, D_, LH, 1 /*relu*/);
    sgemm_nt<<<dim3(128 / 128, ROWS / 128), 256>>>(
        pH1, lin2_w, lin2_b, out, ROWS, 128, D_, 2 /*permute (t,b)->(b,t)*/);
}

// round 2
// speedup vs baseline: 2.6779x; 2.6779x over previous
#include <cuda_runtime.h>
#include <math.h>

// ----- problem dims -----
#define B_    32
#define T_    100
#define NN_   32
#define F_    8
#define D_    256
#define LH    512
#define G4    2048      // 4*LH
#define ROWS  3200      // B_*T_   (row index = t*32 + b)
#define NBLK  128       // persistent LSTM grid

typedef unsigned long long ull;

// ----- device scratch (no allocations allowed) -----
__device__ float d_G  [ROWS * D_];   // relu'd gcn mean embedding
__device__ float d_V  [ROWS * D_];   // value projection
__device__ float d_ATT[ROWS * D_];   // attn_out (== agg)
__device__ float d_X  [ROWS * G4];   // x-projection into LSTM gates
__device__ float d_bihh[G4];         // b_ih + b_hh
__device__ float d_hbuf[2][B_ * LH]; // double-buffered hidden state (b-major)
__device__ float d_L  [ROWS * LH];   // lstm outputs
__device__ float d_H1 [ROWS * D_];   // relu(lin1)
__device__ int   d_bar;              // grid barrier counter

// ======================================================================
// init: zero h[0], barrier counter
// ======================================================================
__global__ void k_zero() {
    int i = blockIdx.x * blockDim.x + threadIdx.x;
    if (i < B_ * LH) d_hbuf[0][i] = 0.0f;
    if (i == 0) d_bar = 0;
}

// d_bihh = b_ih + b_hh
__global__ void k_bihh(const float* __restrict__ bih, const float* __restrict__ bhh) {
    int i = blockIdx.x * blockDim.x + threadIdx.x;
    if (i < G4) d_bihh[i] = bih[i] + bhh[i];
}

// ======================================================================
// G[row,d] = relu( (mean_n traj[b,t,n,:]) @ gcn_w + gcn_b )
// ======================================================================
__global__ void k_G(const float* __restrict__ traj,
                    const float* __restrict__ gw,
                    const float* __restrict__ gb) {
    int row = blockIdx.x;            // t*32 + b
    int t = row >> 5, b = row & 31;
    __shared__ float s[NN_ * F_];
    __shared__ float m[F_];
    int tid = threadIdx.x;

    const float* p = traj + (size_t)((b * T_ + t) * NN_) * F_;
    s[tid] = p[tid];
    __syncthreads();
    if (tid < F_) {
        float acc = 0.0f;
        #pragma unroll
        for (int n = 0; n < NN_; n++) acc += s[n * F_ + tid];
        m[tid] = acc * (1.0f / 32.0f);
    }
    __syncthreads();
    float acc = gb[tid];
    #pragma unroll
    for (int f = 0; f < F_; f++) acc += m[f] * gw[f * D_ + tid];
    d_G[(size_t)row * D_ + tid] = fmaxf(acc, 0.0f);
}

// ======================================================================
// SGEMM-NT:  C[M,N] = A[M,K] @ B[N,K]^T + bias[N]
// flags: 1 = relu epilogue, 2 = permute rows (t*32+b -> (b*T+t)) on store
// ======================================================================
__global__ void __launch_bounds__(256)
sgemm_nt(const float* __restrict__ A, const float* __restrict__ Bm,
         const float* __restrict__ bias, float* __restrict__ C,
         int M, int N, int K, int flags) {
    __shared__ __align__(16) float As[16][128];
    __shared__ __align__(16) float Bs[16][128];

    int tid = threadIdx.x;
    int m0 = blockIdx.y * 128;
    int n0 = blockIdx.x * 128;
    int tm = (tid >> 4) * 8;
    int tn = (tid & 15) * 8;

    float acc[8][8];
    #pragma unroll
    for (int i = 0; i < 8; i++)
        #pragma unroll
        for (int j = 0; j < 8; j++) acc[i][j] = 0.0f;

    for (int k0 = 0; k0 < K; k0 += 16) {
        #pragma unroll
        for (int i = 0; i < 2; i++) {
            int idx = tid + i * 256;
            int r  = idx >> 2;
            int kq = (idx & 3) * 4;
            float4 va = *(const float4*)&A [(size_t)(m0 + r) * K + k0 + kq];
            As[kq + 0][r] = va.x; As[kq + 1][r] = va.y;
            As[kq + 2][r] = va.z; As[kq + 3][r] = va.w;
            float4 vb = *(const float4*)&Bm[(size_t)(n0 + r) * K + k0 + kq];
            Bs[kq + 0][r] = vb.x; Bs[kq + 1][r] = vb.y;
            Bs[kq + 2][r] = vb.z; Bs[kq + 3][r] = vb.w;
        }
        __syncthreads();
        #pragma unroll
        for (int kk = 0; kk < 16; kk++) {
            float a[8], b[8];
            *(float4*)&a[0] = *(const float4*)&As[kk][tm];
            *(float4*)&a[4] = *(const float4*)&As[kk][tm + 4];
            *(float4*)&b[0] = *(const float4*)&Bs[kk][tn];
            *(float4*)&b[4] = *(const float4*)&Bs[kk][tn + 4];
            #pragma unroll
            for (int i = 0; i < 8; i++)
                #pragma unroll
                for (int j = 0; j < 8; j++)
                    acc[i][j] += a[i] * b[j];
        }
        __syncthreads();
    }

    #pragma unroll
    for (int i = 0; i < 8; i++) {
        int m = m0 + tm + i;
        float* crow;
        if (flags & 2) {
            int b = m & 31, tt = m >> 5;
            crow = C + (size_t)(b * T_ + tt) * N;
        } else {
            crow = C + (size_t)m * N;
        }
        #pragma unroll
        for (int j = 0; j < 8; j += 4) {
            float4 v;
            v.x = acc[i][j + 0] + bias[n0 + tn + j + 0];
            v.y = acc[i][j + 1] + bias[n0 + tn + j + 1];
            v.z = acc[i][j + 2] + bias[n0 + tn + j + 2];
            v.w = acc[i][j + 3] + bias[n0 + tn + j + 3];
            if (flags & 1) {
                v.x = fmaxf(v.x, 0.0f); v.y = fmaxf(v.y, 0.0f);
                v.z = fmaxf(v.z, 0.0f); v.w = fmaxf(v.w, 0.0f);
            }
            *(float4*)&crow[n0 + tn + j] = v;
        }
    }
}

// ======================================================================
// Persistent LSTM: ONE kernel runs all 100 timesteps.
// Grid: 128 blocks x 256 threads (one per SM, all resident).
// Block bid owns hidden units j0=bid*4..+3 for all 4 gates (16 w_hh rows),
// so cell state is block-local (lives in shared for the whole kernel).
// w_hh slice (16x512) staged to shared ONCE as f32x2 k-pairs.
// Per step: stage h (32x512 -> shared, k-pair transposed), 8 warps split K,
// packed fma.rn.f32x2 inner loop, shared reduction, pointwise, global h/L
// write, device-wide barrier.
// ======================================================================
__device__ __forceinline__ void ffma2(ull& d, ull a, ull b) {
    asm("fma.rn.f32x2 %0, %1, %2, %0;" : "+l"(d) : "l"(a), "l"(b));
}

#define H2PAD 33
// dynamic shared layout (in float2 / float units)
// ws2  : 16*256 float2      = 32768 B
// h2   : 256*33 float2      = 67584 B
// pacc : 8*16*32 float      = 16384 B
// zbuf : 16*32 float        =  2048 B
// cs   : 4*32 float         =   512 B
#define SM_WS2   0
#define SM_H2    (SM_WS2 + 16 * 256 * 8)
#define SM_PACC  (SM_H2 + 256 * H2PAD * 8)
#define SM_ZBUF  (SM_PACC + 8 * 16 * 32 * 4)
#define SM_CS    (SM_ZBUF + 16 * 32 * 4)
#define SM_TOTAL (SM_CS + 4 * 32 * 4)

__global__ void __launch_bounds__(256, 1)
k_lstm(const float* __restrict__ whh) {
    extern __shared__ char smem[];
    float2* ws2  = (float2*)(smem + SM_WS2);    // [r][k2]  r = gate*4+jj
    float2* h2   = (float2*)(smem + SM_H2);     // [k2][b]  padded stride 33
    float*  pacc = (float*) (smem + SM_PACC);   // [w][r][b]
    float*  zbuf = (float*) (smem + SM_ZBUF);   // [r][b]
    float*  cs   = (float*) (smem + SM_CS);     // [jj][b]

    int tid  = threadIdx.x;
    int lane = tid & 31;
    int wrp  = tid >> 5;                        // 0..7  (K-slice owner)
    int j0   = blockIdx.x * 4;

    // --- stage w_hh slice once: 16 rows x 256 k-pairs ---
    #pragma unroll
    for (int i = 0; i < 16; i++) {
        int r = i;                              // local row = gate*4 + jj
        int rr = (r >> 2) * LH + j0 + (r & 3);
        // tid covers k2 = 0..255
        const float2* src = (const float2*)(whh + (size_t)rr * LH);
        ws2[r * 256 + tid] = src[tid];
    }
    if (tid < 128) cs[tid] = 0.0f;              // cell state = 0
    __syncthreads();

    const int wbase = wrp * 32;                 // this warp's k2 slice

    for (int t = 0; t < T_; t++) {
        const float* hin = d_hbuf[t & 1];
        // --- stage h: [b][512] global -> [k2][b] shared (padded) ---
        #pragma unroll
        for (int i = 0; i < 32; i++) {
            int b  = i;                         // iter = batch
            int k2 = tid;                       // pair index
            float2 v = __ldcg((const float2*)(hin + b * LH + 2 * k2));
            h2[k2 * H2PAD + b] = v;
        }
        __syncthreads();

        // --- packed GEMM: each warp does its 32 k-pairs for all 16 rows ---
        ull acc[16];
        #pragma unroll
        for (int r = 0; r < 16; r++) acc[r] = 0ULL;

        #pragma unroll 2
        for (int k2 = 0; k2 < 32; k2++) {
            ull hv = *(const ull*)&h2[(wbase + k2) * H2PAD + lane];
            #pragma unroll
            for (int r = 0; r < 16; r++) {
                ull wv = *(const ull*)&ws2[r * 256 + wbase + k2];
                ffma2(acc[r], wv, hv);
            }
        }
        // write partials
        #pragma unroll
        for (int r = 0; r < 16; r++) {
            float2 u = *(float2*)&acc[r];
            pacc[(wrp * 16 + r) * 32 + lane] = u.x + u.y;
        }
        __syncthreads();

        // --- reduce across 8 warps + add X, 512 outputs / 256 threads ---
        #pragma unroll
        for (int pass = 0; pass < 2; pass++) {
            int idx = tid + pass * 256;         // 0..511
            int r = idx >> 5, b = idx & 31;
            int rown = (r >> 2) * LH + j0 + (r & 3);
            float z = d_X[(size_t)(t * 32 + b) * G4 + rown];
            #pragma unroll
            for (int w = 0; w < 8; w++)
                z += pacc[(w * 16 + r) * 32 + b];
            zbuf[r * 32 + b] = z;
        }
        __syncthreads();

        // --- pointwise (128 threads): thread -> (b, jj) ---
        if (tid < 128) {
            int b = tid >> 2, jj = tid & 3;
            float zi = zbuf[( 0 + jj) * 32 + b];
            float zf = zbuf[( 4 + jj) * 32 + b];
            float zg = zbuf[( 8 + jj) * 32 + b];
            float zo = zbuf[(12 + jj) * 32 + b];
            float cp = cs[jj * 32 + b];
            float ig = 1.0f / (1.0f + __expf(-zi));
            float fg = 1.0f / (1.0f + __expf(-zf));
            float gg = tanhf(zg);
            float og = 1.0f / (1.0f + __expf(-zo));
            float cn = fg * cp + ig * gg;
            float hn = og * tanhf(cn);
            cs[jj * 32 + b] = cn;
            int j = j0 + jj;
            d_hbuf[(t + 1) & 1][b * LH + j] = hn;
            d_L[(size_t)(t * 32 + b) * LH + j] = hn;
        }

        // --- device-wide barrier ---
        __threadfence();
        __syncthreads();
        if (tid == 0) {
            atomicAdd(&d_bar, 1);
            volatile int* vb = &d_bar;
            while (*vb < NBLK * (t + 1)) { }
        }
        __syncthreads();
    }
}

// ======================================================================
// host side
// ======================================================================
extern "C" void kernel_launch(void* const* d_in, const int* in_sizes, int n_in,
                              void* d_out, int out_size) {
    const float* traj      = (const float*)d_in[0];
    const float* gcn_w     = (const float*)d_in[1];
    const float* gcn_b     = (const float*)d_in[2];
    const float* in_proj_w = (const float*)d_in[3];
    const float* in_proj_b = (const float*)d_in[4];
    const float* out_proj_w= (const float*)d_in[5];
    const float* out_proj_b= (const float*)d_in[6];
    // d_in[7]=va_w, d_in[8]=va_b : provably unused (uniform softmaxes)
    const float* w_ih      = (const float*)d_in[9];
    const float* w_hh      = (const float*)d_in[10];
    const float* b_ih      = (const float*)d_in[11];
    const float* b_hh      = (const float*)d_in[12];
    const float* lin1_w    = (const float*)d_in[13];
    const float* lin1_b    = (const float*)d_in[14];
    const float* lin2_w    = (const float*)d_in[15];
    const float* lin2_b    = (const float*)d_in[16];
    float* out = (float*)d_out;

    float *pG, *pV, *pATT, *pX, *pbihh, *pL, *pH1;
    cudaGetSymbolAddress((void**)&pG,    d_G);
    cudaGetSymbolAddress((void**)&pV,    d_V);
    cudaGetSymbolAddress((void**)&pATT,  d_ATT);
    cudaGetSymbolAddress((void**)&pX,    d_X);
    cudaGetSymbolAddress((void**)&pbihh, d_bihh);
    cudaGetSymbolAddress((void**)&pL,    d_L);
    cudaGetSymbolAddress((void**)&pH1,   d_H1);

    static int smem_set = 0;
    if (!smem_set) {
        cudaFuncSetAttribute(k_lstm, cudaFuncAttributeMaxDynamicSharedMemorySize,
                             SM_TOTAL);
        smem_set = 1;
    }

    k_zero<<<(B_ * LH + 255) / 256, 256>>>();
    k_bihh<<<(G4 + 255) / 256, 256>>>(b_ih, b_hh);
    k_G<<<ROWS, 256>>>(traj, gcn_w, gcn_b);

    // V = G @ Wv^T + bv
    sgemm_nt<<<dim3(D_ / 128, ROWS / 128), 256>>>(
        pG, in_proj_w + (size_t)2 * D_ * D_, in_proj_b + 2 * D_, pV,
        ROWS, D_, D_, 0);
    // ATT = V @ Wop^T + bop   (collapsed attention)
    sgemm_nt<<<dim3(D_ / 128, ROWS / 128), 256>>>(
        pV, out_proj_w, out_proj_b, pATT, ROWS, D_, D_, 0);
    // X = ATT @ w_ih^T + (b_ih+b_hh)
    sgemm_nt<<<dim3(G4 / 128, ROWS / 128), 256>>>(
        pATT, w_ih, pbihh, pX, ROWS, G4, D_, 0);

    // Persistent LSTM: one kernel, all 100 steps
    k_lstm<<<NBLK, 256, SM_TOTAL>>>(w_hh);

    // MLP
    sgemm_nt<<<dim3(D_ / 128, ROWS / 128), 256>>>(
        pL, lin1_w, lin1_b, pH1, ROWS, D_, LH, 1 /*relu*/);
    sgemm_nt<<<dim3(128 / 128, ROWS / 128), 256>>>(
        pH1, lin2_w, lin2_b, out, ROWS, 128, D_, 2 /*permute*/);
}